// round 1
// baseline (speedup 1.0000x reference)
#include <cuda_runtime.h>

// Problem constants (fixed by the reference): B=4, C=80, M=16, N derived at runtime.
#define BB 4
#define CC 80
#define C4 (CC / 4)   // 20 float4 per anchor
#define MM 16
#define NMAX 80000    // N = 76725 for 640x640

#define IMG_W 640.0f
#define IMG_H 640.0f
#define ALPHA_P 0.25f
#define ALPHA_N 0.75f
#define EPS_F 1e-4f
#define BETA_F (1.0f / 9.0f)

// Scratch (no allocations allowed in kernel_launch).
__device__ float  g_labels[BB * NMAX];
__device__ double g_cls_sum[BB];
__device__ float  g_reg_sum[BB];
__device__ int    g_pos[BB];

__global__ void init_kernel() {
    int t = threadIdx.x;
    if (t < BB) {
        g_cls_sum[t] = 0.0;
        g_reg_sum[t] = 0.0f;
        g_pos[t] = 0;
    }
}

// One thread per anchor. blockIdx.y = image.
__global__ void assign_kernel(const float* __restrict__ anchors,
                              const float* __restrict__ annots,
                              const float* __restrict__ regs,
                              int N) {
    const int b = blockIdx.y;
    const int n = blockIdx.x * blockDim.x + threadIdx.x;

    __shared__ float sann[MM * 5];
    __shared__ float s_reg;
    __shared__ int   s_pos;
    if (threadIdx.x < MM * 5) sann[threadIdx.x] = annots[b * MM * 5 + threadIdx.x];
    if (threadIdx.x == 0) { s_reg = 0.0f; s_pos = 0; }
    __syncthreads();

    if (n < N) {
        const long an = (long)b * N + n;
        const float4 a4 = reinterpret_cast<const float4*>(anchors)[an];
        const float a0 = a4.x, a1 = a4.y, a2 = a4.z, a3 = a4.w;

        const bool inside = (a0 > 0.0f) && (a1 > 0.0f) && (a2 < IMG_W) && (a3 < IMG_H);
        const float area_a = (a2 - a0) * (a3 - a1);

        float best = -1.0f;
        int   bidx = 0;
        bool  anyv = false;
#pragma unroll
        for (int j = 0; j < MM; j++) {
            const float g0 = sann[j * 5 + 0];
            const float g1 = sann[j * 5 + 1];
            const float g2 = sann[j * 5 + 2];
            const float g3 = sann[j * 5 + 3];
            const float gc = sann[j * 5 + 4];
            const bool valid = (gc >= 0.0f);
            anyv |= valid;
            const float area_g = (g2 - g0) * (g3 - g1);
            const float lx = fmaxf(a0, g0), ly = fmaxf(a1, g1);
            const float rx = fminf(a2, g2), ry = fminf(a3, g3);
            const float wx = fmaxf(rx - lx, 0.0f), wy = fmaxf(ry - ly, 0.0f);
            const float inter = wx * wy;
            float iou = inter / (area_a + area_g - inter);
            if (!valid) iou = -1.0f;
            if (iou > best) { best = iou; bidx = j; }  // strict > -> first argmax
        }

        const float g0 = sann[bidx * 5 + 0];
        const float g1 = sann[bidx * 5 + 1];
        const float g2 = sann[bidx * 5 + 2];
        const float g3 = sann[bidx * 5 + 3];
        const float gc = sann[bidx * 5 + 4];

        float label = -1.0f;
        if (best < 0.4f) label = 0.0f;
        if (best > 0.5f) label = gc + 1.0f;
        if (!anyv)   label = -1.0f;
        if (!inside) label = -1.0f;

        g_labels[an] = label;

        if (label > 0.0f) {
            // regression targets (match reference op order)
            const float aw = a2 - a0, ah = a3 - a1;
            const float acx = a0 + 0.5f * aw, acy = a1 + 0.5f * ah;
            const float gw = fmaxf(g2 - g0, 1.0f);
            const float gh = fmaxf(g3 - g1, 1.0f);
            const float gcx = g0 + 0.5f * gw, gcy = g1 + 0.5f * gh;
            float t0 = ((gcx - acx) / aw) / 0.1f;
            float t1 = ((gcy - acy) / ah) / 0.1f;
            float t2 = __logf(gw / aw) / 0.2f;
            float t3 = __logf(gh / ah) / 0.2f;

            const float4 r4 = reinterpret_cast<const float4*>(regs)[an];
            float xs[4] = { fabsf(r4.x - t0), fabsf(r4.y - t1),
                            fabsf(r4.z - t2), fabsf(r4.w - t3) };
            float s = 0.0f;
#pragma unroll
            for (int k = 0; k < 4; k++) {
                const float x = xs[k];
                s += (x < BETA_F) ? (0.5f * x * x / BETA_F) : (x - 0.5f * BETA_F);
            }
            atomicAdd(&s_reg, s);
            atomicAdd(&s_pos, 1);
        }
    }
    __syncthreads();
    if (threadIdx.x == 0 && s_pos > 0) {
        atomicAdd(&g_reg_sum[b], s_reg);
        atomicAdd(&g_pos[b], s_pos);
    }
}

// Focal loss over cls_heads. blockIdx.y = image; grid-stride over N*C4 float4.
__global__ void focal_kernel(const float* __restrict__ cls, int N) {
    const int b = blockIdx.y;
    const int per_img = N * C4;
    const float4* __restrict__ base = reinterpret_cast<const float4*>(cls) + (long)b * per_img;
    const float* __restrict__ lab = g_labels + (long)b * N;

    float acc = 0.0f;
    const int stride = gridDim.x * blockDim.x;
    for (int i = blockIdx.x * blockDim.x + threadIdx.x; i < per_img; i += stride) {
        const int anchor = i / C4;                 // C4 is a compile-time constant
        const float label = lab[anchor];
        if (label < 0.0f) continue;                // skip ignored/outside anchors (saves DRAM)
        const float4 p4 = base[i];
        const int c0 = (i - anchor * C4) * 4;
        const int lp = (int)label - 1;             // positive class index (or -1 for label 0)

        float pv[4] = { p4.x, p4.y, p4.z, p4.w };
        float s = 0.0f;
#pragma unroll
        for (int k = 0; k < 4; k++) {
            float p = fminf(fmaxf(pv[k], EPS_F), 1.0f - EPS_F);
            if ((c0 + k) == lp) {
                const float q = 1.0f - p;
                s += ALPHA_P * q * q * (-__logf(p));
            } else {
                s += ALPHA_N * p * p * (-__logf(1.0f - p));
            }
        }
        acc += s;
    }

    // warp reduce, then one shared partial, then one double atomic per block.
    for (int o = 16; o; o >>= 1) acc += __shfl_down_sync(0xffffffffu, acc, o);
    __shared__ float sh;
    if (threadIdx.x == 0) sh = 0.0f;
    __syncthreads();
    if ((threadIdx.x & 31) == 0 && acc != 0.0f) atomicAdd(&sh, acc);
    __syncthreads();
    if (threadIdx.x == 0 && sh != 0.0f) atomicAdd(&g_cls_sum[b], (double)sh);
}

__global__ void finalize_kernel(float* __restrict__ out) {
    if (threadIdx.x == 0) {
        float cls_l = 0.0f, reg_l = 0.0f, nv = 0.0f;
#pragma unroll
        for (int b = 0; b < BB; b++) {
            const float pos = (float)g_pos[b];
            const float clsp = (float)g_cls_sum[b] / fmaxf(pos, 1.0f);
            const float regp = g_reg_sum[b] / fmaxf(4.0f * pos, 1.0f);
            if (pos > 0.0f) { cls_l += clsp; reg_l += regp; nv += 1.0f; }
        }
        nv = fmaxf(nv, 1.0f);
        out[0] = cls_l / nv;
        out[1] = reg_l / nv;
    }
}

extern "C" void kernel_launch(void* const* d_in, const int* in_sizes, int n_in,
                              void* d_out, int out_size) {
    const float* cls     = (const float*)d_in[0];  // (B, N, C)
    const float* regs    = (const float*)d_in[1];  // (B, N, 4)
    const float* anchors = (const float*)d_in[2];  // (B, N, 4)
    const float* annots  = (const float*)d_in[3];  // (B, M, 5)

    const int N = in_sizes[1] / (BB * 4);

    init_kernel<<<1, 32>>>();

    dim3 gridA((N + 255) / 256, BB);
    assign_kernel<<<gridA, 256>>>(anchors, annots, regs, N);

    // 296 blocks/image * 4 images = 1184 blocks of 256 -> ~20 float4/thread,
    // ~1 double atomic per block (contention-free).
    dim3 gridB(296, BB);
    focal_kernel<<<gridB, 256>>>(cls, N);

    finalize_kernel<<<1, 32>>>((float*)d_out);
}